// round 3
// baseline (speedup 1.0000x reference)
#include <cuda_runtime.h>
#include <cuda_bf16.h>
#include <math.h>

// Problem constants
#define T_TOKENS   16384
#define HID        4096
#define NEXP       64
#define TOPK       8
#define RSCALE     2.5f

// Tiling
#define TM   128          // tokens per block
#define KB   32           // k-chunk per smem stage
#define CH   8            // compensated-summation chunk (k terms per TwoSum)
#define NTHREADS 256
#define XPAD 132          // padded token stride in xs

typedef unsigned long long ull;

__device__ __forceinline__ ull ffma2(ull a, ull b, ull c) {
    ull d;
    asm("fma.rn.f32x2 %0, %1, %2, %3;" : "=l"(d) : "l"(a), "l"(b), "l"(c));
    return d;
}
__device__ __forceinline__ ull add2(ull a, ull b) {
    ull d;
    asm("add.rn.f32x2 %0, %1, %2;" : "=l"(d) : "l"(a), "l"(b));
    return d;
}
__device__ __forceinline__ ull pack2(float x) {
    ull d;
    asm("mov.b64 %0, {%1, %1};" : "=l"(d) : "f"(x));
    return d;
}
__device__ __forceinline__ void unpack2(ull v, float& lo, float& hi) {
    asm("mov.b64 {%0, %1}, %2;" : "=f"(lo), "=f"(hi) : "l"(v));
}

// packed lanewise subtraction: a - b = fma(b, -1, a) (exact: -1 multiply is exact)
__device__ __forceinline__ ull sub2(ull a, ull b, ull NEG1) {
    return ffma2(b, NEG1, a);
}

__global__ __launch_bounds__(NTHREADS, 1)
void moe_gate_kernel(const float* __restrict__ x,
                     const float* __restrict__ W,
                     const float* __restrict__ bias,
                     float* __restrict__ out)
{
    __shared__ union SmemU {
        struct {
            float xs[KB][XPAD];   // x transposed: xs[k][token]
            float ws[KB][NEXP];   // W tile: ws[k][expert]
        } g;
        float sc[TM][NEXP + 1];   // sigmoid scores
    } sm;
    __shared__ float bias_s[NEXP];

    const int tid = threadIdx.x;
    const int tx  = tid & 7;    // experts [tx*8, tx*8+8)
    const int ty  = tid >> 3;   // tokens  [ty*4, ty*4+4)
    const int t0  = blockIdx.x * TM;

    if (tid < NEXP) bias_s[tid] = bias[tid];

    const ull NEG1 = pack2(-1.0f);

    // compensated accumulators: sum + compensation, 4 tokens x 4 expert-pairs
    ull s[4][4], c[4][4];
    #pragma unroll
    for (int i = 0; i < 4; ++i)
        #pragma unroll
        for (int j = 0; j < 4; ++j) { s[i][j] = 0ull; c[i][j] = 0ull; }

    const float* xg = x + (size_t)t0 * HID;

    for (int kt = 0; kt < HID / KB; ++kt) {
        // ---- load x tile (128 tokens x 32 k), transpose into xs[k][token]
        #pragma unroll
        for (int p = 0; p < 4; ++p) {
            int flat = tid + p * NTHREADS;
            int tokl = flat >> 3;
            int kq   = flat & 7;
            float4 v = *(const float4*)(xg + (size_t)tokl * HID + kt * KB + kq * 4);
            sm.g.xs[kq * 4 + 0][tokl] = v.x;
            sm.g.xs[kq * 4 + 1][tokl] = v.y;
            sm.g.xs[kq * 4 + 2][tokl] = v.z;
            sm.g.xs[kq * 4 + 3][tokl] = v.w;
        }
        // ---- load W tile (32 k x 64 experts)
        #pragma unroll
        for (int p = 0; p < 2; ++p) {
            int flat = tid + p * NTHREADS;
            int row  = flat >> 4;
            int c4   = flat & 15;
            float4 v = *(const float4*)(W + (size_t)(kt * KB + row) * NEXP + c4 * 4);
            *(float4*)&sm.g.ws[row][c4 * 4] = v;
        }
        __syncthreads();

        // ---- compute: chunks of CH=8 k-terms, fp32 fma chain per chunk,
        //      TwoSum-compensated accumulation of chunk sums (error ~1e-7 total)
        #pragma unroll
        for (int kc = 0; kc < KB; kc += CH) {
            ull ch[4][4];
            #pragma unroll
            for (int i = 0; i < 4; ++i)
                #pragma unroll
                for (int j = 0; j < 4; ++j) ch[i][j] = 0ull;

            #pragma unroll
            for (int q = 0; q < CH; ++q) {
                int kk = kc + q;
                float4 a4 = *(const float4*)&sm.g.xs[kk][ty * 4];
                ull a[4];
                a[0] = pack2(a4.x); a[1] = pack2(a4.y);
                a[2] = pack2(a4.z); a[3] = pack2(a4.w);
                ulonglong2 b01 = *(const ulonglong2*)&sm.g.ws[kk][tx * 8];
                ulonglong2 b23 = *(const ulonglong2*)&sm.g.ws[kk][tx * 8 + 4];
                ull b[4] = {b01.x, b01.y, b23.x, b23.y};
                #pragma unroll
                for (int i = 0; i < 4; ++i)
                    #pragma unroll
                    for (int j = 0; j < 4; ++j)
                        ch[i][j] = ffma2(a[i], b[j], ch[i][j]);
            }

            // TwoSum: (s, c) += ch   (branchless Knuth, lanewise packed)
            #pragma unroll
            for (int i = 0; i < 4; ++i)
                #pragma unroll
                for (int j = 0; j < 4; ++j) {
                    ull sp = add2(s[i][j], ch[i][j]);
                    ull z  = sub2(sp, s[i][j], NEG1);
                    ull e1 = sub2(ch[i][j], z, NEG1);
                    ull t  = sub2(sp, z, NEG1);
                    ull e2 = sub2(s[i][j], t, NEG1);
                    c[i][j] = add2(c[i][j], add2(e1, e2));
                    s[i][j] = sp;
                }
        }
        __syncthreads();
    }

    // ---- epilogue: logits = s + c, sigmoid, write scores to smem
    #pragma unroll
    for (int i = 0; i < 4; ++i) {
        int tok = ty * 4 + i;
        #pragma unroll
        for (int j = 0; j < 4; ++j) {
            ull l2 = add2(s[i][j], c[i][j]);
            float lo, hi;
            unpack2(l2, lo, hi);
            int e = tx * 8 + 2 * j;
            sm.sc[tok][e]     = 1.0f / (1.0f + expf(-lo));
            sm.sc[tok][e + 1] = 1.0f / (1.0f + expf(-hi));
        }
    }
    __syncthreads();

    // ---- top-8 per token (stable: ties keep lowest expert index first)
    if (tid < TM) {
        const int tok = tid;
        float bv[TOPK];
        int   bi[TOPK];
        #pragma unroll
        for (int k = 0; k < TOPK; ++k) { bv[k] = -INFINITY; bi[k] = 0; }

        for (int e = 0; e < NEXP; ++e) {
            float sv = sm.sc[tok][e] + bias_s[e];
            if (sv > bv[TOPK - 1]) {
                bv[TOPK - 1] = sv; bi[TOPK - 1] = e;
                #pragma unroll
                for (int j = TOPK - 1; j > 0; --j) {
                    if (bv[j] > bv[j - 1]) {
                        float tv = bv[j]; bv[j] = bv[j - 1]; bv[j - 1] = tv;
                        int   ti = bi[j]; bi[j] = bi[j - 1]; bi[j - 1] = ti;
                    }
                }
            }
        }

        float wsel[TOPK];
        float sum = 1e-20f;
        #pragma unroll
        for (int k = 0; k < TOPK; ++k) {
            wsel[k] = sm.sc[tok][bi[k]];
            sum += wsel[k];
        }
        float inv = RSCALE / sum;

        const size_t gt = (size_t)(t0 + tok);
        float* out_idx = out + gt * TOPK;
        float* out_w   = out + (size_t)T_TOKENS * TOPK + gt * TOPK;
        #pragma unroll
        for (int k = 0; k < TOPK; ++k) {
            out_idx[k] = (float)bi[k];
            out_w[k]   = wsel[k] * inv;
        }
    }
}

extern "C" void kernel_launch(void* const* d_in, const int* in_sizes, int n_in,
                              void* d_out, int out_size)
{
    const float* x    = (const float*)d_in[0];
    const float* W    = (const float*)d_in[1];
    const float* bias = (const float*)d_in[2];
    float* out = (float*)d_out;

    dim3 grid(T_TOKENS / TM);
    dim3 block(NTHREADS);
    moe_gate_kernel<<<grid, block>>>(x, W, bias, out);
}